// round 2
// baseline (speedup 1.0000x reference)
#include <cuda_runtime.h>

static constexpr int NN   = 25000;
static constexpr int NE   = 500000;
static constexpr int CH   = 128;
static constexpr int OUTW = 2048;

// ---------------- scratch (static device globals; no allocation allowed) ----
__device__ float g_h[NN * CH];                 // 12.8 MB
__device__ float g_x3[(size_t)NE * 64];        // 128 MB
__device__ float g_w[(size_t)NE * 512];        // 1.024 GB
__device__ float g_agg[(size_t)NN * 2048];     // 204.8 MB
__device__ int   g_cnt[NN];
__device__ int   g_off[NN + 1];
__device__ int   g_cur[NN];
__device__ int   g_sorted[NE];
__device__ int   g_send[NE];
__device__ int   g_recv[NE];
__device__ int   g_is64;

__device__ __forceinline__ float silu(float x) {
    return x / (1.0f + __expf(-x));
}

// ---------------- edge_index dtype detection + conversion -------------------
// JAX with default x64-disabled config downcasts the reference's int64
// edge_index to int32. Detect which layout the buffer actually has: for
// little-endian int64 with values < 2^31, every odd int32 word is zero.
__global__ void k_detect(const int* __restrict__ ei) {
    int is64 = 1;
    for (int i = 0; i < 8; i++)
        if (ei[2 * i + 1] != 0) is64 = 0;
    g_is64 = is64;
}
__global__ void k_convert(const int* __restrict__ ei) {
    int e = blockIdx.x * 256 + threadIdx.x;
    if (e >= NE) return;
    int s, r;
    if (g_is64) {
        const long long* p = (const long long*)ei;
        s = (int)p[e];
        r = (int)p[NE + e];
    } else {
        s = ei[e];
        r = ei[NE + e];
    }
    // defensive clamp (valid data is already in range)
    s = min(max(s, 0), NN - 1);
    r = min(max(r, 0), NN - 1);
    g_send[e] = s;
    g_recv[e] = r;
}

// ---------------- h = node_feats @ W_up  (25000x128 @ 128x128) --------------
__global__ void k_h(const float* __restrict__ nf, const float* __restrict__ Wup) {
    __shared__ float fs[8 * CH];
    const int n0 = blockIdx.x * 8;
    const int t  = threadIdx.x;  // 128
    for (int i = t; i < 8 * CH; i += 128) {
        int n = n0 + i / CH;
        fs[i] = (n < NN) ? nf[(size_t)n * CH + (i & (CH - 1))] : 0.0f;
    }
    __syncthreads();
    float acc[8];
#pragma unroll
    for (int i = 0; i < 8; i++) acc[i] = 0.0f;
    for (int k = 0; k < CH; k++) {
        float wv = __ldg(&Wup[k * CH + t]);
#pragma unroll
        for (int i = 0; i < 8; i++) acc[i] += fs[i * CH + k] * wv;
    }
#pragma unroll
    for (int i = 0; i < 8; i++) {
        int n = n0 + i;
        if (n < NN) g_h[(size_t)n * CH + t] = acc[i];
    }
}

// ---------------- radial layers 1-3 fused: x3 = silu(silu(silu(ef@W1)@W2)@W3)
__global__ void __launch_bounds__(256) k_r123(const float* __restrict__ ef,
                                              const float* __restrict__ W1,
                                              const float* __restrict__ W2,
                                              const float* __restrict__ W3) {
    __shared__ float efs[64 * 8];
    __shared__ float bufA[64 * 64];
    __shared__ float bufB[64 * 64];
    const int t  = threadIdx.x;
    const int e0 = blockIdx.x * 64;
    for (int i = t; i < 64 * 8; i += 256) {
        int e = e0 + i / 8;
        efs[i] = (e < NE) ? ef[(size_t)e * 8 + (i & 7)] : 0.0f;
    }
    __syncthreads();
    const int rg   = t >> 5;   // 0..7 -> 8 rows each
    const int lane = t & 31;   // cols lane*2, lane*2+1

    // layer 1 (K=8)
    {
        float a0[8], a1[8];
#pragma unroll
        for (int i = 0; i < 8; i++) { a0[i] = 0.f; a1[i] = 0.f; }
        for (int k = 0; k < 8; k++) {
            float w0 = __ldg(&W1[k * 64 + lane * 2]);
            float w1 = __ldg(&W1[k * 64 + lane * 2 + 1]);
#pragma unroll
            for (int i = 0; i < 8; i++) {
                float a = efs[(rg * 8 + i) * 8 + k];
                a0[i] += a * w0; a1[i] += a * w1;
            }
        }
#pragma unroll
        for (int i = 0; i < 8; i++) {
            bufA[(rg * 8 + i) * 64 + lane * 2]     = silu(a0[i]);
            bufA[(rg * 8 + i) * 64 + lane * 2 + 1] = silu(a1[i]);
        }
    }
    __syncthreads();
    // layer 2 (K=64)
    {
        float a0[8], a1[8];
#pragma unroll
        for (int i = 0; i < 8; i++) { a0[i] = 0.f; a1[i] = 0.f; }
        for (int k = 0; k < 64; k++) {
            float w0 = __ldg(&W2[k * 64 + lane * 2]);
            float w1 = __ldg(&W2[k * 64 + lane * 2 + 1]);
#pragma unroll
            for (int i = 0; i < 8; i++) {
                float a = bufA[(rg * 8 + i) * 64 + k];
                a0[i] += a * w0; a1[i] += a * w1;
            }
        }
#pragma unroll
        for (int i = 0; i < 8; i++) {
            bufB[(rg * 8 + i) * 64 + lane * 2]     = silu(a0[i]);
            bufB[(rg * 8 + i) * 64 + lane * 2 + 1] = silu(a1[i]);
        }
    }
    __syncthreads();
    // layer 3 (K=64) -> global x3
    {
        float a0[8], a1[8];
#pragma unroll
        for (int i = 0; i < 8; i++) { a0[i] = 0.f; a1[i] = 0.f; }
        for (int k = 0; k < 64; k++) {
            float w0 = __ldg(&W3[k * 64 + lane * 2]);
            float w1 = __ldg(&W3[k * 64 + lane * 2 + 1]);
#pragma unroll
            for (int i = 0; i < 8; i++) {
                float a = bufB[(rg * 8 + i) * 64 + k];
                a0[i] += a * w0; a1[i] += a * w1;
            }
        }
#pragma unroll
        for (int i = 0; i < 8; i++) {
            int e = e0 + rg * 8 + i;
            if (e < NE) {
                g_x3[(size_t)e * 64 + lane * 2]     = silu(a0[i]);
                g_x3[(size_t)e * 64 + lane * 2 + 1] = silu(a1[i]);
            }
        }
    }
}

// ---------------- layer 4 GEMM fused with sender-gather:
//   w[e, p*128+c] = (x3[e,:] @ W4[:, p*128+c]) * h[sender[e], c]
__global__ void __launch_bounds__(256) k_r4(const float* __restrict__ W4) {
    __shared__ float As[128 * 64];
    const int t  = threadIdx.x;
    const int e0 = blockIdx.x * 128;
    const int by = blockIdx.y;  // path 0..3 -> cols by*128..+127 of W4
    for (int i = t; i < 128 * 64; i += 256) {
        int e = e0 + (i >> 6);
        As[i] = (e < NE) ? g_x3[(size_t)e * 64 + (i & 63)] : 0.0f;
    }
    __syncthreads();
    const int tr = t >> 4;   // 0..15, rows tr*8..+7
    const int tc = t & 15;   // 0..15, cols tc*8..+7
    float acc[8][8];
#pragma unroll
    for (int i = 0; i < 8; i++)
#pragma unroll
        for (int j = 0; j < 8; j++) acc[i][j] = 0.0f;

    const float* Wb = W4 + by * 128;
    for (int k = 0; k < 64; k++) {
        float4 b0 = __ldg((const float4*)&Wb[(size_t)k * 512 + tc * 8]);
        float4 b1 = __ldg((const float4*)&Wb[(size_t)k * 512 + tc * 8 + 4]);
        float b[8] = {b0.x, b0.y, b0.z, b0.w, b1.x, b1.y, b1.z, b1.w};
        float a[8];
#pragma unroll
        for (int i = 0; i < 8; i++) a[i] = As[(tr * 8 + i) * 64 + k];
#pragma unroll
        for (int i = 0; i < 8; i++)
#pragma unroll
            for (int j = 0; j < 8; j++) acc[i][j] += a[i] * b[j];
    }

#pragma unroll
    for (int i = 0; i < 8; i++) {
        int e = e0 + tr * 8 + i;
        if (e < NE) {
            int s = g_send[e];
            float4 h0 = __ldg((const float4*)&g_h[(size_t)s * CH + tc * 8]);
            float4 h1 = __ldg((const float4*)&g_h[(size_t)s * CH + tc * 8 + 4]);
            float* wo = g_w + (size_t)e * 512 + by * 128 + tc * 8;
            float4 r0 = make_float4(acc[i][0] * h0.x, acc[i][1] * h0.y,
                                    acc[i][2] * h0.z, acc[i][3] * h0.w);
            float4 r1 = make_float4(acc[i][4] * h1.x, acc[i][5] * h1.y,
                                    acc[i][6] * h1.z, acc[i][7] * h1.w);
            *(float4*)&wo[0] = r0;
            *(float4*)&wo[4] = r1;
        }
    }
}

// ---------------- counting sort of edges by receiver -------------------------
__global__ void k_zero() {
    int i = blockIdx.x * 256 + threadIdx.x;
    if (i < NN) g_cnt[i] = 0;
}
__global__ void k_hist() {
    int e = blockIdx.x * 256 + threadIdx.x;
    if (e < NE) atomicAdd(&g_cnt[g_recv[e]], 1);
}
__global__ void k_scan() {  // single block, 1024 threads
    __shared__ int s[1024];
    const int t = threadIdx.x;
    const int CK = 25;  // 1024*25 = 25600 >= NN
    const int base = t * CK;
    int loc[CK];
    int sum = 0;
#pragma unroll
    for (int i = 0; i < CK; i++) {
        int idx = base + i;
        int c = (idx < NN) ? g_cnt[idx] : 0;
        loc[i] = sum;
        sum += c;
    }
    s[t] = sum;
    __syncthreads();
    for (int d = 1; d < 1024; d <<= 1) {
        int v = (t >= d) ? s[t - d] : 0;
        __syncthreads();
        s[t] += v;
        __syncthreads();
    }
    int pre = (t == 0) ? 0 : s[t - 1];
#pragma unroll
    for (int i = 0; i < CK; i++) {
        int idx = base + i;
        if (idx < NN) {
            int o = pre + loc[i];
            g_off[idx] = o;
            g_cur[idx] = o;
        }
    }
    if (t == 1023) g_off[NN] = s[1023];
}
__global__ void k_scatter() {
    int e = blockIdx.x * 256 + threadIdx.x;
    if (e < NE) {
        int pos = atomicAdd(&g_cur[g_recv[e]], 1);
        g_sorted[pos] = e;
    }
}

// ---------------- segmented aggregation: agg[n,m,c] = sum_e sh[e,m]*w[e,p(m),c]
__global__ void k_agg(const float* __restrict__ ea) {
    const int n = blockIdx.x;
    const int c = threadIdx.x;  // 128
    float acc[16];
#pragma unroll
    for (int m = 0; m < 16; m++) acc[m] = 0.0f;
    const int lo = g_off[n], hi = g_off[n + 1];
    for (int i = lo; i < hi; i++) {
        int e = g_sorted[i];
        const float* wr = g_w + (size_t)e * 512;
        float w0 = wr[c], w1 = wr[128 + c], w2 = wr[256 + c], w3 = wr[384 + c];
        const float* sh = ea + (size_t)e * 16;
        acc[0] += __ldg(&sh[0]) * w0;
#pragma unroll
        for (int m = 1; m < 4; m++) acc[m] += __ldg(&sh[m]) * w1;
#pragma unroll
        for (int m = 4; m < 9; m++) acc[m] += __ldg(&sh[m]) * w2;
#pragma unroll
        for (int m = 9; m < 16; m++) acc[m] += __ldg(&sh[m]) * w3;
    }
    const float inv = 1.0f / 20.0f;  // AVG_NUM_NEIGHBORS
#pragma unroll
    for (int m = 0; m < 16; m++)
        g_agg[(size_t)n * 2048 + m * 128 + c] = acc[m] * inv;
}

// ---------------- out transform per path: out[n, COLOFF + d*ML + m]
//   = sum_c agg[n, OFFM+m, c] * Wl[c, d]
template <int ML, int NB, int OFFM, int COLOFF>
__global__ void __launch_bounds__(256) k_out(const float* __restrict__ Wl,
                                             float* __restrict__ out) {
    constexpr int NR = ML * NB;  // <= 64
    __shared__ float As[64 * 128];
    const int t  = threadIdx.x;
    const int n0 = blockIdx.x * NB;
    for (int i = t; i < 64 * 128; i += 256) {
        int r = i >> 7, c = i & 127;
        float v = 0.0f;
        if (r < NR) {
            int n = n0 + r / ML;
            if (n < NN) v = g_agg[(size_t)n * 2048 + (OFFM + r % ML) * 128 + c];
        }
        As[i] = v;
    }
    __syncthreads();
    const int rg = t >> 5, lane = t & 31;
    float acc[8][4];
#pragma unroll
    for (int i = 0; i < 8; i++)
#pragma unroll
        for (int j = 0; j < 4; j++) acc[i][j] = 0.0f;
    for (int c = 0; c < 128; c++) {
        float4 w = __ldg((const float4*)&Wl[c * 128 + lane * 4]);
#pragma unroll
        for (int i = 0; i < 8; i++) {
            float a = As[(rg * 8 + i) * 128 + c];
            acc[i][0] += a * w.x;
            acc[i][1] += a * w.y;
            acc[i][2] += a * w.z;
            acc[i][3] += a * w.w;
        }
    }
#pragma unroll
    for (int i = 0; i < 8; i++) {
        int r = rg * 8 + i;
        if (r < NR) {
            int n = n0 + r / ML;
            if (n < NN) {
                int m = r % ML;
                float* op = out + (size_t)n * OUTW + COLOFF + m;
#pragma unroll
                for (int j = 0; j < 4; j++) {
                    int d = lane * 4 + j;
                    op[(size_t)d * ML] = acc[i][j];
                }
            }
        }
    }
}

// ---------------- one-body term added to path-0 block (cols 0..127) ----------
__global__ void k_ob(const float* __restrict__ pf, const float* __restrict__ nf,
                     const float* __restrict__ lc, const float* __restrict__ Wp,
                     const float* __restrict__ Wn, const float* __restrict__ Wc,
                     float* __restrict__ out) {
    __shared__ float pfs[16 * 16];
    __shared__ float nfs[16 * 128];
    __shared__ float lcs[16];
    const int t  = threadIdx.x;  // 128
    const int n0 = blockIdx.x * 16;
    for (int i = t; i < 16 * 16; i += 128) {
        int n = n0 + i / 16;
        pfs[i] = (n < NN) ? pf[(size_t)n * 16 + (i & 15)] * 0.1f : 0.0f;  // /FIELD_NORM
    }
    for (int i = t; i < 16 * 128; i += 128) {
        int n = n0 + i / 128;
        nfs[i] = (n < NN) ? nf[(size_t)n * 128 + (i & 127)] : 0.0f;
    }
    if (t < 16) {
        int n = n0 + t;
        lcs[t] = (n < NN) ? lc[n] : 0.0f;
    }
    __syncthreads();
    float acc[16];
    float wc = __ldg(&Wc[t]);
#pragma unroll
    for (int i = 0; i < 16; i++) acc[i] = lcs[i] * wc;
    for (int k = 0; k < 16; k++) {
        float wv = __ldg(&Wp[k * 128 + t]);
#pragma unroll
        for (int i = 0; i < 16; i++) acc[i] += pfs[i * 16 + k] * wv;
    }
    for (int k = 0; k < 128; k++) {
        float wv = __ldg(&Wn[k * 128 + t]);
#pragma unroll
        for (int i = 0; i < 16; i++) acc[i] += nfs[i * 128 + k] * wv;
    }
#pragma unroll
    for (int i = 0; i < 16; i++) {
        int n = n0 + i;
        if (n < NN) out[(size_t)n * OUTW + t] += acc[i];
    }
}

// ---------------- launch -----------------------------------------------------
extern "C" void kernel_launch(void* const* d_in, const int* in_sizes, int n_in,
                              void* d_out, int out_size) {
    const float* node_feats = (const float*)d_in[1];
    const float* edge_attrs = (const float*)d_in[2];
    const float* edge_feats = (const float*)d_in[3];
    const int*   edge_index = (const int*)d_in[4];   // dtype auto-detected
    const float* potential  = (const float*)d_in[5];
    const float* charges    = (const float*)d_in[6];
    const float* W_up = (const float*)d_in[7];
    const float* W1   = (const float*)d_in[8];
    const float* W2   = (const float*)d_in[9];
    const float* W3   = (const float*)d_in[10];
    const float* W4   = (const float*)d_in[11];
    const float* Wout = (const float*)d_in[12];
    const float* Wp   = (const float*)d_in[13];
    const float* Wn   = (const float*)d_in[14];
    const float* Wc   = (const float*)d_in[15];
    float*       out  = (float*)d_out;

    // edge_index dtype detection + int32 conversion
    k_detect<<<1, 1>>>(edge_index);
    k_convert<<<(NE + 255) / 256, 256>>>(edge_index);

    // sort prep (independent of h / radial)
    k_zero<<<(NN + 255) / 256, 256>>>();
    k_hist<<<(NE + 255) / 256, 256>>>();
    k_scan<<<1, 1024>>>();
    k_scatter<<<(NE + 255) / 256, 256>>>();

    // node embedding + radial MLP
    k_h<<<(NN + 7) / 8, 128>>>(node_feats, W_up);
    k_r123<<<(NE + 63) / 64, 256>>>(edge_feats, W1, W2, W3);
    k_r4<<<dim3((NE + 127) / 128, 4), 256>>>(W4);

    // segmented aggregation
    k_agg<<<NN, 128>>>(edge_attrs);

    // per-path out transform (writes every output element exactly once)
    k_out<1, 64, 0, 0><<<(NN + 63) / 64, 256>>>(Wout, out);
    k_out<3, 21, 1, 128><<<(NN + 20) / 21, 256>>>(Wout + 1 * CH * CH, out);
    k_out<5, 12, 4, 512><<<(NN + 11) / 12, 256>>>(Wout + 2 * CH * CH, out);
    k_out<7, 9, 9, 1152><<<(NN + 8) / 9, 256>>>(Wout + 3 * CH * CH, out);

    // one-body correction into cols [0,128)
    k_ob<<<(NN + 15) / 16, 128>>>(potential, node_feats, charges, Wp, Wn, Wc, out);
}

// round 3
// speedup vs baseline: 1.2008x; 1.2008x over previous
#include <cuda_runtime.h>

static constexpr int NN   = 25000;
static constexpr int NE   = 500000;
static constexpr int CH   = 128;
static constexpr int OUTW = 2048;

// ---------------- scratch (static device globals; no allocation allowed) ----
__device__ float g_h[NN * CH];                 // 12.8 MB
__device__ float g_x3[(size_t)NE * 64];        // 128 MB
__device__ float g_w[(size_t)NE * 512];        // 1.024 GB
__device__ float g_agg[(size_t)NN * 2048];     // 204.8 MB
__device__ int   g_cnt[NN];
__device__ int   g_off[NN + 1];
__device__ int   g_cur[NN];
__device__ int   g_sorted[NE];
__device__ int   g_send[NE];
__device__ int   g_recv[NE];

__device__ __forceinline__ float silu(float x) {
    return __fdividef(x, 1.0f + __expf(-x));
}

// packed f32x2 helpers (Blackwell; PTX-only, ptxas never emits these itself)
__device__ __forceinline__ unsigned long long bcast2(float a) {
    unsigned long long r;
    asm("mov.b64 %0, {%1, %1};" : "=l"(r) : "f"(a));
    return r;
}
__device__ __forceinline__ void fma2(unsigned long long& acc, unsigned long long a,
                                     unsigned long long b) {
    asm("fma.rn.f32x2 %0, %1, %2, %0;" : "+l"(acc) : "l"(a), "l"(b));
}
__device__ __forceinline__ float2 unpack2(unsigned long long v) {
    float lo, hi;
    asm("mov.b64 {%0, %1}, %2;" : "=f"(lo), "=f"(hi) : "l"(v));
    return make_float2(lo, hi);
}

// ---------------- edge_index dtype detect + int32 conversion ----------------
// JAX with x64 disabled silently downcasts the reference's int64 edge_index to
// int32. For little-endian int64 with node ids < 2^31 every odd int32 word is 0.
__global__ void k_convert(const int* __restrict__ ei) {
    int e = blockIdx.x * 256 + threadIdx.x;
    if (e >= NE) return;
    bool is64 = true;
#pragma unroll
    for (int i = 0; i < 8; i++) is64 &= (__ldg(&ei[2 * i + 1]) == 0);
    int s, r;
    if (is64) {
        const long long* p = (const long long*)ei;
        s = (int)p[e];
        r = (int)p[NE + e];
    } else {
        s = ei[e];
        r = ei[NE + e];
    }
    s = min(max(s, 0), NN - 1);
    r = min(max(r, 0), NN - 1);
    g_send[e] = s;
    g_recv[e] = r;
}

// ---------------- h = node_feats @ W_up  (25000x128 @ 128x128) --------------
__global__ void k_h(const float* __restrict__ nf, const float* __restrict__ Wup) {
    __shared__ float fs[8 * CH];
    const int n0 = blockIdx.x * 8;
    const int t  = threadIdx.x;  // 128
    for (int i = t; i < 8 * CH; i += 128) {
        int n = n0 + i / CH;
        fs[i] = (n < NN) ? nf[(size_t)n * CH + (i & (CH - 1))] : 0.0f;
    }
    __syncthreads();
    float acc[8];
#pragma unroll
    for (int i = 0; i < 8; i++) acc[i] = 0.0f;
    for (int k = 0; k < CH; k++) {
        float wv = __ldg(&Wup[k * CH + t]);
#pragma unroll
        for (int i = 0; i < 8; i++) acc[i] += fs[i * CH + k] * wv;
    }
#pragma unroll
    for (int i = 0; i < 8; i++) {
        int n = n0 + i;
        if (n < NN) g_h[(size_t)n * CH + t] = acc[i];
    }
}

// ---------------- radial layers 1-3 fused: x3 = silu(silu(silu(ef@W1)@W2)@W3)
// 64-row tile, 128 threads; thread = 8 rows x 4 cols; f32x2 packed FMA.
__global__ void __launch_bounds__(128) k_r123(const float* __restrict__ ef,
                                              const float* __restrict__ W1,
                                              const float* __restrict__ W2,
                                              const float* __restrict__ W3) {
    __shared__ float efs[64 * 8];
    __shared__ float bufA[64 * 64];
    __shared__ float bufB[64 * 64];
    const int t  = threadIdx.x;
    const int e0 = blockIdx.x * 64;
    for (int i = t; i < 64 * 8; i += 128) {
        int e = e0 + i / 8;
        efs[i] = (e < NE) ? ef[(size_t)e * 8 + (i & 7)] : 0.0f;
    }
    __syncthreads();
    const int tr = t >> 4;   // 0..7 -> rows tr*8..+7
    const int tc = t & 15;   // cols tc*4..+3

    // ---- layer 1 (K=8) ----
    {
        unsigned long long acc[8][2];
#pragma unroll
        for (int i = 0; i < 8; i++) { acc[i][0] = 0ULL; acc[i][1] = 0ULL; }
#pragma unroll
        for (int k = 0; k < 8; k++) {
            ulonglong2 w = __ldg((const ulonglong2*)&W1[k * 64 + tc * 4]);
#pragma unroll
            for (int i = 0; i < 8; i++) {
                unsigned long long a2 = bcast2(efs[(tr * 8 + i) * 8 + k]);
                fma2(acc[i][0], a2, w.x);
                fma2(acc[i][1], a2, w.y);
            }
        }
#pragma unroll
        for (int i = 0; i < 8; i++) {
            float2 p0 = unpack2(acc[i][0]), p1 = unpack2(acc[i][1]);
            float* d = &bufA[(tr * 8 + i) * 64 + tc * 4];
            d[0] = silu(p0.x); d[1] = silu(p0.y);
            d[2] = silu(p1.x); d[3] = silu(p1.y);
        }
    }
    __syncthreads();
    // ---- layer 2 (K=64) ----
    {
        unsigned long long acc[8][2];
#pragma unroll
        for (int i = 0; i < 8; i++) { acc[i][0] = 0ULL; acc[i][1] = 0ULL; }
        for (int k = 0; k < 64; k++) {
            ulonglong2 w = __ldg((const ulonglong2*)&W2[k * 64 + tc * 4]);
#pragma unroll
            for (int i = 0; i < 8; i++) {
                unsigned long long a2 = bcast2(bufA[(tr * 8 + i) * 64 + k]);
                fma2(acc[i][0], a2, w.x);
                fma2(acc[i][1], a2, w.y);
            }
        }
        __syncthreads();
#pragma unroll
        for (int i = 0; i < 8; i++) {
            float2 p0 = unpack2(acc[i][0]), p1 = unpack2(acc[i][1]);
            float* d = &bufB[(tr * 8 + i) * 64 + tc * 4];
            d[0] = silu(p0.x); d[1] = silu(p0.y);
            d[2] = silu(p1.x); d[3] = silu(p1.y);
        }
    }
    __syncthreads();
    // ---- layer 3 (K=64) -> global x3 ----
    {
        unsigned long long acc[8][2];
#pragma unroll
        for (int i = 0; i < 8; i++) { acc[i][0] = 0ULL; acc[i][1] = 0ULL; }
        for (int k = 0; k < 64; k++) {
            ulonglong2 w = __ldg((const ulonglong2*)&W3[k * 64 + tc * 4]);
#pragma unroll
            for (int i = 0; i < 8; i++) {
                unsigned long long a2 = bcast2(bufB[(tr * 8 + i) * 64 + k]);
                fma2(acc[i][0], a2, w.x);
                fma2(acc[i][1], a2, w.y);
            }
        }
#pragma unroll
        for (int i = 0; i < 8; i++) {
            int e = e0 + tr * 8 + i;
            if (e < NE) {
                float2 p0 = unpack2(acc[i][0]), p1 = unpack2(acc[i][1]);
                float4 v = make_float4(silu(p0.x), silu(p0.y), silu(p1.x), silu(p1.y));
                *(float4*)&g_x3[(size_t)e * 64 + tc * 4] = v;
            }
        }
    }
}

// ---------------- layer 4 GEMM fused with sender-gather (f32x2):
//   w[e, p*128+c] = (x3[e,:] @ W4[:, p*128+c]) * h[sender[e], c]
// grid = (4 paths, edge tiles): path varies fastest -> x3 tile L2-resident.
__global__ void __launch_bounds__(256) k_r4(const float* __restrict__ W4) {
    __shared__ float As[128 * 64];
    const int t  = threadIdx.x;
    const int e0 = blockIdx.y * 128;
    const int by = blockIdx.x;  // path 0..3
    for (int i = t; i < 128 * 64; i += 256) {
        int e = e0 + (i >> 6);
        As[i] = (e < NE) ? g_x3[(size_t)e * 64 + (i & 63)] : 0.0f;
    }
    __syncthreads();
    const int tr = t >> 4;   // rows tr*8..+7
    const int tc = t & 15;   // cols tc*8..+7
    unsigned long long acc[8][4];
#pragma unroll
    for (int i = 0; i < 8; i++)
#pragma unroll
        for (int j = 0; j < 4; j++) acc[i][j] = 0ULL;

    const float* Wb = W4 + by * 128;
    for (int k = 0; k < 64; k++) {
        ulonglong2 b01 = __ldg((const ulonglong2*)&Wb[(size_t)k * 512 + tc * 8]);
        ulonglong2 b23 = __ldg((const ulonglong2*)&Wb[(size_t)k * 512 + tc * 8 + 4]);
#pragma unroll
        for (int i = 0; i < 8; i++) {
            unsigned long long a2 = bcast2(As[(tr * 8 + i) * 64 + k]);
            fma2(acc[i][0], a2, b01.x);
            fma2(acc[i][1], a2, b01.y);
            fma2(acc[i][2], a2, b23.x);
            fma2(acc[i][3], a2, b23.y);
        }
    }

#pragma unroll
    for (int i = 0; i < 8; i++) {
        int e = e0 + tr * 8 + i;
        if (e < NE) {
            int s = g_send[e];
            float4 h0 = __ldg((const float4*)&g_h[(size_t)s * CH + tc * 8]);
            float4 h1 = __ldg((const float4*)&g_h[(size_t)s * CH + tc * 8 + 4]);
            float2 a0 = unpack2(acc[i][0]), a1 = unpack2(acc[i][1]);
            float2 a2 = unpack2(acc[i][2]), a3 = unpack2(acc[i][3]);
            float* wo = g_w + (size_t)e * 512 + by * 128 + tc * 8;
            *(float4*)&wo[0] = make_float4(a0.x * h0.x, a0.y * h0.y,
                                           a1.x * h0.z, a1.y * h0.w);
            *(float4*)&wo[4] = make_float4(a2.x * h1.x, a2.y * h1.y,
                                           a3.x * h1.z, a3.y * h1.w);
        }
    }
}

// ---------------- counting sort of edges by receiver -------------------------
__global__ void k_zero() {
    int i = blockIdx.x * 256 + threadIdx.x;
    if (i < NN) g_cnt[i] = 0;
}
__global__ void k_hist() {
    int e = blockIdx.x * 256 + threadIdx.x;
    if (e < NE) atomicAdd(&g_cnt[g_recv[e]], 1);
}
__global__ void k_scan() {  // single block, 1024 threads
    __shared__ int s[1024];
    const int t = threadIdx.x;
    const int CK = 25;  // 1024*25 = 25600 >= NN
    const int base = t * CK;
    int loc[CK];
    int sum = 0;
#pragma unroll
    for (int i = 0; i < CK; i++) {
        int idx = base + i;
        int c = (idx < NN) ? g_cnt[idx] : 0;
        loc[i] = sum;
        sum += c;
    }
    s[t] = sum;
    __syncthreads();
    for (int d = 1; d < 1024; d <<= 1) {
        int v = (t >= d) ? s[t - d] : 0;
        __syncthreads();
        s[t] += v;
        __syncthreads();
    }
    int pre = (t == 0) ? 0 : s[t - 1];
#pragma unroll
    for (int i = 0; i < CK; i++) {
        int idx = base + i;
        if (idx < NN) {
            int o = pre + loc[i];
            g_off[idx] = o;
            g_cur[idx] = o;
        }
    }
    if (t == 1023) g_off[NN] = s[1023];
}
__global__ void k_scatter() {
    int e = blockIdx.x * 256 + threadIdx.x;
    if (e < NE) {
        int pos = atomicAdd(&g_cur[g_recv[e]], 1);
        g_sorted[pos] = e;
    }
}

// ---------------- segmented aggregation: agg[n,m,c] = sum_e sh[e,m]*w[e,p(m),c]
__global__ void k_agg(const float* __restrict__ ea) {
    const int n = blockIdx.x;
    const int c = threadIdx.x;  // 128
    float acc[16];
#pragma unroll
    for (int m = 0; m < 16; m++) acc[m] = 0.0f;
    const int lo = g_off[n], hi = g_off[n + 1];
    for (int i = lo; i < hi; i++) {
        int e = g_sorted[i];
        const float* wr = g_w + (size_t)e * 512;
        float w0 = wr[c], w1 = wr[128 + c], w2 = wr[256 + c], w3 = wr[384 + c];
        const float* sh = ea + (size_t)e * 16;
        acc[0] += __ldg(&sh[0]) * w0;
#pragma unroll
        for (int m = 1; m < 4; m++) acc[m] += __ldg(&sh[m]) * w1;
#pragma unroll
        for (int m = 4; m < 9; m++) acc[m] += __ldg(&sh[m]) * w2;
#pragma unroll
        for (int m = 9; m < 16; m++) acc[m] += __ldg(&sh[m]) * w3;
    }
    const float inv = 1.0f / 20.0f;  // AVG_NUM_NEIGHBORS
#pragma unroll
    for (int m = 0; m < 16; m++)
        g_agg[(size_t)n * 2048 + m * 128 + c] = acc[m] * inv;
}

// ---------------- out transform per path (f32x2): out[n, COLOFF + d*ML + m]
//   = sum_c agg[n, OFFM+m, c] * Wl[c, d]
template <int ML, int NB, int OFFM, int COLOFF>
__global__ void __launch_bounds__(256) k_out(const float* __restrict__ Wl,
                                             float* __restrict__ out) {
    constexpr int NR = ML * NB;  // <= 64
    __shared__ float As[64 * 128];
    const int t  = threadIdx.x;
    const int n0 = blockIdx.x * NB;
    for (int i = t; i < 64 * 128; i += 256) {
        int r = i >> 7, c = i & 127;
        float v = 0.0f;
        if (r < NR) {
            int n = n0 + r / ML;
            if (n < NN) v = g_agg[(size_t)n * 2048 + (OFFM + r % ML) * 128 + c];
        }
        As[i] = v;
    }
    __syncthreads();
    const int rg = t >> 5, lane = t & 31;
    unsigned long long acc[8][2];
#pragma unroll
    for (int i = 0; i < 8; i++) { acc[i][0] = 0ULL; acc[i][1] = 0ULL; }
    for (int c = 0; c < 128; c++) {
        ulonglong2 w = __ldg((const ulonglong2*)&Wl[c * 128 + lane * 4]);
#pragma unroll
        for (int i = 0; i < 8; i++) {
            unsigned long long a2 = bcast2(As[(rg * 8 + i) * 128 + c]);
            fma2(acc[i][0], a2, w.x);
            fma2(acc[i][1], a2, w.y);
        }
    }
#pragma unroll
    for (int i = 0; i < 8; i++) {
        int r = rg * 8 + i;
        if (r < NR) {
            int n = n0 + r / ML;
            if (n < NN) {
                int m = r % ML;
                float* op = out + (size_t)n * OUTW + COLOFF + m;
                float2 p0 = unpack2(acc[i][0]), p1 = unpack2(acc[i][1]);
                float v[4] = {p0.x, p0.y, p1.x, p1.y};
#pragma unroll
                for (int j = 0; j < 4; j++) {
                    int d = lane * 4 + j;
                    op[(size_t)d * ML] = v[j];
                }
            }
        }
    }
}

// ---------------- one-body term added to path-0 block (cols 0..127) ----------
__global__ void k_ob(const float* __restrict__ pf, const float* __restrict__ nf,
                     const float* __restrict__ lc, const float* __restrict__ Wp,
                     const float* __restrict__ Wn, const float* __restrict__ Wc,
                     float* __restrict__ out) {
    __shared__ float pfs[16 * 16];
    __shared__ float nfs[16 * 128];
    __shared__ float lcs[16];
    const int t  = threadIdx.x;  // 128
    const int n0 = blockIdx.x * 16;
    for (int i = t; i < 16 * 16; i += 128) {
        int n = n0 + i / 16;
        pfs[i] = (n < NN) ? pf[(size_t)n * 16 + (i & 15)] * 0.1f : 0.0f;
    }
    for (int i = t; i < 16 * 128; i += 128) {
        int n = n0 + i / 128;
        nfs[i] = (n < NN) ? nf[(size_t)n * 128 + (i & 127)] : 0.0f;
    }
    if (t < 16) {
        int n = n0 + t;
        lcs[t] = (n < NN) ? lc[n] : 0.0f;
    }
    __syncthreads();
    float acc[16];
    float wc = __ldg(&Wc[t]);
#pragma unroll
    for (int i = 0; i < 16; i++) acc[i] = lcs[i] * wc;
    for (int k = 0; k < 16; k++) {
        float wv = __ldg(&Wp[k * 128 + t]);
#pragma unroll
        for (int i = 0; i < 16; i++) acc[i] += pfs[i * 16 + k] * wv;
    }
    for (int k = 0; k < 128; k++) {
        float wv = __ldg(&Wn[k * 128 + t]);
#pragma unroll
        for (int i = 0; i < 16; i++) acc[i] += nfs[i * 128 + k] * wv;
    }
#pragma unroll
    for (int i = 0; i < 16; i++) {
        int n = n0 + i;
        if (n < NN) out[(size_t)n * OUTW + t] += acc[i];
    }
}

// ---------------- launch -----------------------------------------------------
extern "C" void kernel_launch(void* const* d_in, const int* in_sizes, int n_in,
                              void* d_out, int out_size) {
    const float* node_feats = (const float*)d_in[1];
    const float* edge_attrs = (const float*)d_in[2];
    const float* edge_feats = (const float*)d_in[3];
    const int*   edge_index = (const int*)d_in[4];   // dtype auto-detected
    const float* potential  = (const float*)d_in[5];
    const float* charges    = (const float*)d_in[6];
    const float* W_up = (const float*)d_in[7];
    const float* W1   = (const float*)d_in[8];
    const float* W2   = (const float*)d_in[9];
    const float* W3   = (const float*)d_in[10];
    const float* W4   = (const float*)d_in[11];
    const float* Wout = (const float*)d_in[12];
    const float* Wp   = (const float*)d_in[13];
    const float* Wn   = (const float*)d_in[14];
    const float* Wc   = (const float*)d_in[15];
    float*       out  = (float*)d_out;

    // launch order places k_r4 at index 3 so ncu (-s 5 w/ ~2 harness launches)
    // captures the dominant kernel.
    k_convert<<<(NE + 255) / 256, 256>>>(edge_index);            // 0
    k_h<<<(NN + 7) / 8, 128>>>(node_feats, W_up);                // 1
    k_r123<<<(NE + 63) / 64, 128>>>(edge_feats, W1, W2, W3);     // 2
    k_r4<<<dim3(4, (NE + 127) / 128), 256>>>(W4);                // 3 <- profiled

    // sort prep
    k_zero<<<(NN + 255) / 256, 256>>>();
    k_hist<<<(NE + 255) / 256, 256>>>();
    k_scan<<<1, 1024>>>();
    k_scatter<<<(NE + 255) / 256, 256>>>();

    // segmented aggregation
    k_agg<<<NN, 128>>>(edge_attrs);

    // per-path out transform (writes every output element exactly once)
    k_out<1, 64, 0, 0><<<(NN + 63) / 64, 256>>>(Wout, out);
    k_out<3, 21, 1, 128><<<(NN + 20) / 21, 256>>>(Wout + 1 * CH * CH, out);
    k_out<5, 12, 4, 512><<<(NN + 11) / 12, 256>>>(Wout + 2 * CH * CH, out);
    k_out<7, 9, 9, 1152><<<(NN + 8) / 9, 256>>>(Wout + 3 * CH * CH, out);

    // one-body correction into cols [0,128)
    k_ob<<<(NN + 15) / 16, 128>>>(potential, node_feats, charges, Wp, Wn, Wc, out);
}